// round 2
// baseline (speedup 1.0000x reference)
#include <cuda_runtime.h>
#include <math.h>
#include <stdint.h>

#define SEQ 512
#define BATCH 64
#define IN_DIM 512
#define HID 1024

#define NCTA 128   // persistent recurrence grid (<=148 SMs -> all co-resident)
#define RTHREADS 128
#define KC 64      // k-chunk staged in smem

// ---------------- scratch (static device globals; no runtime allocation) ----
__device__ float g_x[3][(size_t)SEQ * BATCH * HID]; // xz, xr, xm  (402 MB)
__device__ float g_h[BATCH * HID];
__device__ float g_rh[BATCH * HID];
__device__ unsigned g_cnt; // zero-init; self-resets -> replay safe
__device__ unsigned g_gen; // monotonically increasing across replays (relative compare)

__device__ __forceinline__ float sigmoidf_(float x) {
    return 1.0f / (1.0f + expf(-x));
}

// ---------------------------------------------------------------------------
// init: copy init_h -> g_h
// ---------------------------------------------------------------------------
__global__ void init_h_kernel(const float* __restrict__ h0) {
    int i = blockIdx.x * blockDim.x + threadIdx.x;
    for (; i < BATCH * HID; i += gridDim.x * blockDim.x)
        g_h[i] = h0[i];
}

// ---------------------------------------------------------------------------
// Precompute x-projections: g_x[g] = E @ Wg[0:IN] + bg
// Tiled fp32 GEMM: BM=128, BN=64, BK=32, 256 threads, 8x4 microtile.
// ---------------------------------------------------------------------------
#define BM 128
#define BN 64
#define BK 32

__global__ void __launch_bounds__(256) x_gemm_kernel(
    const float* __restrict__ E,
    const float* __restrict__ Wz, const float* __restrict__ bz,
    const float* __restrict__ Wr, const float* __restrict__ br,
    const float* __restrict__ Wm, const float* __restrict__ bm)
{
    const int gate = blockIdx.z;
    const float* W    = (gate == 0) ? Wz : (gate == 1) ? Wr : Wm;
    const float* bias = (gate == 0) ? bz : (gate == 1) ? br : bm;
    float* OUT = g_x[gate];

    __shared__ float as[BK][BM + 4]; // A transposed [k][m], pad 132
    __shared__ float bs[BK][BN + 4]; // [k][n], pad 68

    const int tid   = threadIdx.x;
    const int mBase = blockIdx.y * BM;
    const int nBase = blockIdx.x * BN;
    const int tx = tid & 15;  // n dir (4 cols each)
    const int ty = tid >> 4;  // m dir (8 rows each)

    float acc[8][4];
#pragma unroll
    for (int i = 0; i < 8; i++)
#pragma unroll
        for (int j = 0; j < 4; j++) acc[i][j] = 0.f;

    for (int k0 = 0; k0 < IN_DIM; k0 += BK) {
        // load A tile 128x32 (transpose into smem)
#pragma unroll
        for (int i = 0; i < 4; i++) {
            int f = tid + i * 256;          // 1024 float4 slots
            int m = f >> 3;
            int kq = f & 7;
            float4 v = *(const float4*)&E[(size_t)(mBase + m) * IN_DIM + k0 + kq * 4];
            as[kq * 4 + 0][m] = v.x;
            as[kq * 4 + 1][m] = v.y;
            as[kq * 4 + 2][m] = v.z;
            as[kq * 4 + 3][m] = v.w;
        }
        // load B tile 32x64
#pragma unroll
        for (int i = 0; i < 2; i++) {
            int f = tid + i * 256;          // 512 float4 slots
            int r = f >> 4;
            int cq = f & 15;
            float4 v = *(const float4*)&W[(size_t)(k0 + r) * HID + nBase + cq * 4];
            *(float4*)&bs[r][cq * 4] = v;
        }
        __syncthreads();

#pragma unroll 8
        for (int k = 0; k < BK; k++) {
            float a[8], b[4];
#pragma unroll
            for (int i = 0; i < 8; i++) a[i] = as[k][ty * 8 + i];
#pragma unroll
            for (int j = 0; j < 4; j++) b[j] = bs[k][tx * 4 + j];
#pragma unroll
            for (int i = 0; i < 8; i++)
#pragma unroll
                for (int j = 0; j < 4; j++) acc[i][j] += a[i] * b[j];
        }
        __syncthreads();
    }

    const float4 bv = *(const float4*)&bias[nBase + tx * 4];
#pragma unroll
    for (int i = 0; i < 8; i++) {
        int m = mBase + ty * 8 + i;
        float4 o;
        o.x = acc[i][0] + bv.x;
        o.y = acc[i][1] + bv.y;
        o.z = acc[i][2] + bv.z;
        o.w = acc[i][3] + bv.w;
        *(float4*)&OUT[(size_t)m * HID + nBase + tx * 4] = o;
    }
}

// ---------------------------------------------------------------------------
// Global barrier (generation based, replay-safe)
// ---------------------------------------------------------------------------
__device__ __forceinline__ void gbar(unsigned target) {
    __threadfence();       // every thread: publish my stores (L2) before arrival
    __syncthreads();
    if (threadIdx.x == 0) {
        unsigned old = atomicAdd(&g_cnt, 1u);
        if (old == NCTA - 1u) {
            atomicExch(&g_cnt, 0u);
            __threadfence();
            atomicExch(&g_gen, target);
        } else {
            while ((int)(atomicAdd(&g_gen, 0u) - target) < 0) { __nanosleep(32); }
        }
    }
    __syncthreads();
    __threadfence();       // acquire side
}

// ---------------------------------------------------------------------------
// Persistent recurrence kernel.
// 128 CTAs x 128 threads. CTA owns 8 output columns (j0..j0+7), all 64 batches.
// Phase A: z (threads 0..63) and r (64..127), each gate split-K x2.
//   thread tile: 4b x 4j, b = bq + {0,16,32,48}, j = j0 + jq*4 + {0..3}
// Phase B: m gate, split-K x4 over all 128 threads, owners = threads 0..31
//   (same (b,j) slots as the z threads, which hold z in registers).
// ---------------------------------------------------------------------------
__global__ void __launch_bounds__(RTHREADS) gru_rec_kernel(
    const float* __restrict__ Wz,
    const float* __restrict__ Wr,
    const float* __restrict__ Wm,
    float* __restrict__ out)
{
    __shared__ float hs[BATCH][KC + 1];   // staged h / rh chunk
    __shared__ float w0s[KC][8];
    __shared__ float w1s[KC][8];
    __shared__ float red[1536];           // split-K partial exchange
    __shared__ unsigned s_g0;

    const int tid = threadIdx.x;
    const int cta = blockIdx.x;
    const int j0  = cta * 8;

    const int s   = tid & 31;     // output slot
    const int bq  = s & 15;
    const int jq  = s >> 4;
    const int jq4 = jq * 4;
    const int jcol = j0 + jq4;

    const int g  = tid >> 6;        // phase A gate: 0=z, 1=r
    const int kh = (tid >> 5) & 1;  // phase A split-K half
    const int kh2 = tid >> 5;       // phase B split-K quarter (0..3)

    if (tid == 0) s_g0 = atomicAdd(&g_gen, 0u);
    __syncthreads();
    unsigned mygen = s_g0;

    float zr[4][4]; // z (g==0,kh==0) or r (g==1,kh==0), kept across phase B
#pragma unroll
    for (int i = 0; i < 4; i++)
#pragma unroll
        for (int l = 0; l < 4; l++) zr[i][l] = 0.f;

    for (int t = 0; t < SEQ; t++) {
        // ================= Phase A: z and r gate matmuls =================
        float acc[4][4];
#pragma unroll
        for (int i = 0; i < 4; i++)
#pragma unroll
            for (int l = 0; l < 4; l++) acc[i][l] = 0.f;

        for (int c = 0; c < HID / KC; c++) {
            const int k0 = c * KC;
            // stage h chunk [64][KC]
#pragma unroll
            for (int i = 0; i < 8; i++) {
                int f = tid + i * 128;     // 1024 float4 slots
                int b = f >> 4;
                int kq = f & 15;
                float4 v = __ldcg((const float4*)&g_h[b * HID + k0 + kq * 4]);
                hs[b][kq * 4 + 0] = v.x;
                hs[b][kq * 4 + 1] = v.y;
                hs[b][kq * 4 + 2] = v.z;
                hs[b][kq * 4 + 3] = v.w;
            }
            // stage Wz / Wr chunk [KC][8] each
#pragma unroll
            for (int i = 0; i < 2; i++) {
                int f = tid + i * 128;     // 256 float4 slots
                int gg = f >> 7;
                int r2 = f & 127;
                int k  = r2 >> 1;
                int jv = r2 & 1;
                const float* W = gg ? Wr : Wz;
                float4 v = *(const float4*)&W[(size_t)(IN_DIM + k0 + k) * HID + j0 + jv * 4];
                float* dst = gg ? &w1s[k][jv * 4] : &w0s[k][jv * 4];
                *(float4*)dst = v;
            }
            __syncthreads();

            const float (*ws)[8] = g ? w1s : w0s;
            const int kbeg = kh * (KC / 2);
#pragma unroll 8
            for (int k = kbeg; k < kbeg + KC / 2; k++) {
                float a0 = hs[bq][k];
                float a1 = hs[bq + 16][k];
                float a2 = hs[bq + 32][k];
                float a3 = hs[bq + 48][k];
                float w0 = ws[k][jq4 + 0];
                float w1 = ws[k][jq4 + 1];
                float w2 = ws[k][jq4 + 2];
                float w3 = ws[k][jq4 + 3];
                acc[0][0] += a0 * w0; acc[0][1] += a0 * w1; acc[0][2] += a0 * w2; acc[0][3] += a0 * w3;
                acc[1][0] += a1 * w0; acc[1][1] += a1 * w1; acc[1][2] += a1 * w2; acc[1][3] += a1 * w3;
                acc[2][0] += a2 * w0; acc[2][1] += a2 * w1; acc[2][2] += a2 * w2; acc[2][3] += a2 * w3;
                acc[3][0] += a3 * w0; acc[3][1] += a3 * w1; acc[3][2] += a3 * w2; acc[3][3] += a3 * w3;
            }
            __syncthreads();
        }

        // split-K combine + activations
        if (kh) {
            int base = (g * 32 + s) * 16;
#pragma unroll
            for (int i = 0; i < 4; i++)
#pragma unroll
                for (int l = 0; l < 4; l++) red[base + i * 4 + l] = acc[i][l];
        }
        __syncthreads();
        if (!kh) {
            int base = (g * 32 + s) * 16;
#pragma unroll
            for (int i = 0; i < 4; i++) {
                int b = bq + 16 * i;
                float4 x4 = __ldcg((const float4*)&g_x[g][((size_t)t * BATCH + b) * HID + jcol]);
                zr[i][0] = sigmoidf_(x4.x + acc[i][0] + red[base + i * 4 + 0]);
                zr[i][1] = sigmoidf_(x4.y + acc[i][1] + red[base + i * 4 + 1]);
                zr[i][2] = sigmoidf_(x4.z + acc[i][2] + red[base + i * 4 + 2]);
                zr[i][3] = sigmoidf_(x4.w + acc[i][3] + red[base + i * 4 + 3]);
            }
            if (g == 1) {
                // r threads: rh = r * h  (elementwise over hidden index)
#pragma unroll
                for (int i = 0; i < 4; i++) {
                    int b = bq + 16 * i;
                    float4 h4 = __ldcg((const float4*)&g_h[b * HID + jcol]);
                    float4 rh4;
                    rh4.x = zr[i][0] * h4.x;
                    rh4.y = zr[i][1] * h4.y;
                    rh4.z = zr[i][2] * h4.z;
                    rh4.w = zr[i][3] * h4.w;
                    __stcg((float4*)&g_rh[b * HID + jcol], rh4);
                }
            }
        }
        mygen++;
        gbar(mygen);   // rh now globally visible

        // ================= Phase B: m gate matmul (rh @ Wm_h) =============
        float accm[4][4];
#pragma unroll
        for (int i = 0; i < 4; i++)
#pragma unroll
            for (int l = 0; l < 4; l++) accm[i][l] = 0.f;

        for (int c = 0; c < HID / KC; c++) {
            const int k0 = c * KC;
#pragma unroll
            for (int i = 0; i < 8; i++) {
                int f = tid + i * 128;
                int b = f >> 4;
                int kq = f & 15;
                float4 v = __ldcg((const float4*)&g_rh[b * HID + k0 + kq * 4]);
                hs[b][kq * 4 + 0] = v.x;
                hs[b][kq * 4 + 1] = v.y;
                hs[b][kq * 4 + 2] = v.z;
                hs[b][kq * 4 + 3] = v.w;
            }
            {
                int k  = tid >> 1;   // 128 float4 slots
                int jv = tid & 1;
                float4 v = *(const float4*)&Wm[(size_t)(IN_DIM + k0 + k) * HID + j0 + jv * 4];
                *(float4*)&w0s[k][jv * 4] = v;
            }
            __syncthreads();

            const int kbeg = kh2 * (KC / 4);
#pragma unroll 8
            for (int k = kbeg; k < kbeg + KC / 4; k++) {
                float a0 = hs[bq][k];
                float a1 = hs[bq + 16][k];
                float a2 = hs[bq + 32][k];
                float a3 = hs[bq + 48][k];
                float w0 = w0s[k][jq4 + 0];
                float w1 = w0s[k][jq4 + 1];
                float w2 = w0s[k][jq4 + 2];
                float w3 = w0s[k][jq4 + 3];
                accm[0][0] += a0 * w0; accm[0][1] += a0 * w1; accm[0][2] += a0 * w2; accm[0][3] += a0 * w3;
                accm[1][0] += a1 * w0; accm[1][1] += a1 * w1; accm[1][2] += a1 * w2; accm[1][3] += a1 * w3;
                accm[2][0] += a2 * w0; accm[2][1] += a2 * w1; accm[2][2] += a2 * w2; accm[2][3] += a2 * w3;
                accm[3][0] += a3 * w0; accm[3][1] += a3 * w1; accm[3][2] += a3 * w2; accm[3][3] += a3 * w3;
            }
            __syncthreads();
        }

        if (kh2) {
            int base = ((kh2 - 1) * 32 + s) * 16;
#pragma unroll
            for (int i = 0; i < 4; i++)
#pragma unroll
                for (int l = 0; l < 4; l++) red[base + i * 4 + l] = accm[i][l];
        }
        __syncthreads();
        if (kh2 == 0) {
            // owners (threads 0..31), hold z in zr
#pragma unroll
            for (int i = 0; i < 4; i++) {
                int b = bq + 16 * i;
                float4 xm4 = __ldcg((const float4*)&g_x[2][((size_t)t * BATCH + b) * HID + jcol]);
                float4 h4  = __ldcg((const float4*)&g_h[b * HID + jcol]);
                float pre[4], hn[4];
#pragma unroll
                for (int l = 0; l < 4; l++) {
                    float xv = (l == 0) ? xm4.x : (l == 1) ? xm4.y : (l == 2) ? xm4.z : xm4.w;
                    pre[l] = xv + accm[i][l]
                           + red[(0 * 32 + s) * 16 + i * 4 + l]
                           + red[(1 * 32 + s) * 16 + i * 4 + l]
                           + red[(2 * 32 + s) * 16 + i * 4 + l];
                }
                float hv[4] = {h4.x, h4.y, h4.z, h4.w};
#pragma unroll
                for (int l = 0; l < 4; l++) {
                    float ht = tanhf(pre[l]);
                    hn[l] = hv[l] + zr[i][l] * (ht - hv[l]);
                }
                float4 hn4 = make_float4(hn[0], hn[1], hn[2], hn[3]);
                __stcg((float4*)&g_h[b * HID + jcol], hn4);
                __stcg((float4*)&out[(size_t)b * SEQ * HID + (size_t)t * HID + jcol], hn4);
            }
        }
        mygen++;
        gbar(mygen);   // h_new globally visible for next step
    }
}

// ---------------------------------------------------------------------------
extern "C" void kernel_launch(void* const* d_in, const int* in_sizes, int n_in,
                              void* d_out, int out_size)
{
    const float* E  = (const float*)d_in[0];
    const float* h0 = (const float*)d_in[1];
    const float* Wz = (const float*)d_in[2];
    const float* bz = (const float*)d_in[3];
    const float* Wr = (const float*)d_in[4];
    const float* br = (const float*)d_in[5];
    const float* Wm = (const float*)d_in[6];
    const float* bm = (const float*)d_in[7];
    float* out = (float*)d_out;

    init_h_kernel<<<64, 256>>>(h0);

    dim3 gg(HID / BN, (SEQ * BATCH) / BM, 3);
    x_gemm_kernel<<<gg, 256>>>(E, Wz, bz, Wr, br, Wm, bm);

    gru_rec_kernel<<<NCTA, RTHREADS>>>(Wz, Wr, Wm, out);
}

// round 4
// speedup vs baseline: 2.3345x; 2.3345x over previous
#include <cuda_runtime.h>
#include <math.h>
#include <stdint.h>

#define SEQ 512
#define BATCH 64
#define IN_DIM 512
#define HID 1024

#define NCTA 128
#define RTHREADS 256
#define KC 64
#define NCHUNK (HID / KC)

// smem partition (floats)
#define HS_STRIDE 68               // KC row pad: 16B-aligned rows
#define HS_SIZE   (KC * HS_STRIDE) // 4352
#define W_OFF     (2 * HS_SIZE)    // 8704
#define W_GATE    (HID * 8)        // 8192
#define RED_OFF   (W_OFF + 3 * W_GATE)  // 33280
#define SMEM_FLOATS (RED_OFF + 3584)    // 36864
#define SMEM_BYTES  (SMEM_FLOATS * 4)   // 147456

// ---------------- scratch ----------------
__device__ float g_x[3][(size_t)SEQ * BATCH * HID];
__device__ float g_h[BATCH * HID];
__device__ float g_rh[BATCH * HID];
__device__ unsigned g_cnt;
__device__ unsigned g_gen;

__device__ __forceinline__ float sigmoidf_(float x) { return 1.0f / (1.0f + expf(-x)); }

// ---------------- f32x2 helpers ----------------
__device__ __forceinline__ void ffma2(unsigned long long& d, unsigned long long a, unsigned long long w) {
    asm("fma.rn.f32x2 %0, %1, %2, %0;" : "+l"(d) : "l"(a), "l"(w));
}
__device__ __forceinline__ unsigned long long addf32x2(unsigned long long a, unsigned long long b) {
    unsigned long long d;
    asm("add.rn.f32x2 %0, %1, %2;" : "=l"(d) : "l"(a), "l"(b));
    return d;
}
__device__ __forceinline__ unsigned long long dup2(float w) {
    unsigned long long d;
    unsigned u = __float_as_uint(w);
    asm("mov.b64 %0, {%1, %1};" : "=l"(d) : "r"(u));
    return d;
}
__device__ __forceinline__ void unpk(unsigned long long v, float& lo, float& hi) {
    unsigned x, y;
    asm("mov.b64 {%0, %1}, %2;" : "=r"(x), "=r"(y) : "l"(v));
    lo = __uint_as_float(x);
    hi = __uint_as_float(y);
}

// ---------------- sync helpers ----------------
__device__ __forceinline__ unsigned ld_acq(unsigned* p) {
    unsigned v;
    asm volatile("ld.acquire.gpu.u32 %0, [%1];" : "=r"(v) : "l"(p) : "memory");
    return v;
}
// Canonical fence-before-signal global barrier (every thread fences; thread 0
// arrives/waits). Matches the passing v1 pattern.
__device__ __forceinline__ void gbar(unsigned target) {
    __threadfence();       // publish this thread's stores at gpu scope
    __syncthreads();
    if (threadIdx.x == 0) {
        unsigned old;
        asm volatile("atom.acq_rel.gpu.add.u32 %0, [%1], %2;"
                     : "=r"(old) : "l"(&g_cnt), "r"(1u) : "memory");
        if (old == NCTA - 1u) {
            asm volatile("st.relaxed.gpu.u32 [%0], %1;" :: "l"(&g_cnt), "r"(0u) : "memory");
            asm volatile("st.release.gpu.u32 [%0], %1;" :: "l"(&g_gen), "r"(target) : "memory");
        } else {
            while (1) {
                unsigned v = ld_acq(&g_gen);
                if ((int)(v - target) >= 0) break;
                __nanosleep(64);
            }
        }
    }
    __syncthreads();
    __threadfence();       // acquire side
}

// ---------------------------------------------------------------------------
__global__ void init_h_kernel(const float* __restrict__ h0) {
    int i = blockIdx.x * blockDim.x + threadIdx.x;
    for (; i < BATCH * HID; i += gridDim.x * blockDim.x)
        g_h[i] = h0[i];
}

// ---------------------------------------------------------------------------
// Precompute x-projections (known-good from round 1)
// ---------------------------------------------------------------------------
#define BM 128
#define BN 64
#define BK 32

__global__ void __launch_bounds__(256) x_gemm_kernel(
    const float* __restrict__ E,
    const float* __restrict__ Wz, const float* __restrict__ bz,
    const float* __restrict__ Wr, const float* __restrict__ br,
    const float* __restrict__ Wm, const float* __restrict__ bm)
{
    const int gate = blockIdx.z;
    const float* W    = (gate == 0) ? Wz : (gate == 1) ? Wr : Wm;
    const float* bias = (gate == 0) ? bz : (gate == 1) ? br : bm;
    float* OUT = g_x[gate];

    __shared__ float as[BK][BM + 4];
    __shared__ float bs[BK][BN + 4];

    const int tid   = threadIdx.x;
    const int mBase = blockIdx.y * BM;
    const int nBase = blockIdx.x * BN;
    const int tx = tid & 15;
    const int ty = tid >> 4;

    float acc[8][4];
#pragma unroll
    for (int i = 0; i < 8; i++)
#pragma unroll
        for (int j = 0; j < 4; j++) acc[i][j] = 0.f;

    for (int k0 = 0; k0 < IN_DIM; k0 += BK) {
#pragma unroll
        for (int i = 0; i < 4; i++) {
            int f = tid + i * 256;
            int m = f >> 3;
            int kq = f & 7;
            float4 v = *(const float4*)&E[(size_t)(mBase + m) * IN_DIM + k0 + kq * 4];
            as[kq * 4 + 0][m] = v.x;
            as[kq * 4 + 1][m] = v.y;
            as[kq * 4 + 2][m] = v.z;
            as[kq * 4 + 3][m] = v.w;
        }
#pragma unroll
        for (int i = 0; i < 2; i++) {
            int f = tid + i * 256;
            int r = f >> 4;
            int cq = f & 15;
            float4 v = *(const float4*)&W[(size_t)(k0 + r) * HID + nBase + cq * 4];
            *(float4*)&bs[r][cq * 4] = v;
        }
        __syncthreads();

#pragma unroll 8
        for (int k = 0; k < BK; k++) {
            float a[8], b[4];
#pragma unroll
            for (int i = 0; i < 8; i++) a[i] = as[k][ty * 8 + i];
#pragma unroll
            for (int j = 0; j < 4; j++) b[j] = bs[k][tx * 4 + j];
#pragma unroll
            for (int i = 0; i < 8; i++)
#pragma unroll
                for (int j = 0; j < 4; j++) acc[i][j] += a[i] * b[j];
        }
        __syncthreads();
    }

    const float4 bv = *(const float4*)&bias[nBase + tx * 4];
#pragma unroll
    for (int i = 0; i < 8; i++) {
        int m = mBase + ty * 8 + i;
        float4 o;
        o.x = acc[i][0] + bv.x;
        o.y = acc[i][1] + bv.y;
        o.z = acc[i][2] + bv.z;
        o.w = acc[i][3] + bv.w;
        *(float4*)&OUT[(size_t)m * HID + nBase + tx * 4] = o;
    }
}

// ---------------------------------------------------------------------------
// Recurrence v3: 128 CTAs x 256 threads, persistent weights, double-buffered
// h staging, FFMA2 inner loop. (v2 + weight chunk-offset fix + barrier fences)
// ---------------------------------------------------------------------------
__device__ __forceinline__ void stage_load(const float* __restrict__ src, int k0,
                                           int sb, int skq, float4 pv[4]) {
#pragma unroll
    for (int i = 0; i < 4; i++) {
        int kq = i * 4 + skq;
        pv[i] = __ldcg((const float4*)&src[(size_t)sb * HID + k0 + kq * 4]);
    }
}
__device__ __forceinline__ void stage_store(float* __restrict__ hb,
                                            int sb, int skq, const float4 pv[4]) {
#pragma unroll
    for (int i = 0; i < 4; i++) {
        int kq = i * 4 + skq;
        hb[(kq * 4 + 0) * HS_STRIDE + sb] = pv[i].x;
        hb[(kq * 4 + 1) * HS_STRIDE + sb] = pv[i].y;
        hb[(kq * 4 + 2) * HS_STRIDE + sb] = pv[i].z;
        hb[(kq * 4 + 3) * HS_STRIDE + sb] = pv[i].w;
    }
}

// hb: staged h chunk [KC][HS_STRIDE]; wb: weight rows for THIS chunk ([KC][8]).
// kbeg: within-chunk k offset of this warp's split-K slice.
template <int KN>
__device__ __forceinline__ void mm_chunk(const float* __restrict__ hb,
                                         const float* __restrict__ wb,
                                         int kbeg, int bq, int jq,
                                         unsigned long long acc[8]) {
    const float* hp = hb + kbeg * HS_STRIDE + bq * 4;
    const float* wp = wb + kbeg * 8 + jq * 4;
#pragma unroll
    for (int i = 0; i < KN; i++) {
        ulonglong2 a = *(const ulonglong2*)(hp + i * HS_STRIDE);
        float4 wv = *(const float4*)(wp + i * 8);
        unsigned long long w0 = dup2(wv.x), w1 = dup2(wv.y), w2 = dup2(wv.z), w3 = dup2(wv.w);
        ffma2(acc[0], a.x, w0);
        ffma2(acc[1], a.x, w1);
        ffma2(acc[2], a.x, w2);
        ffma2(acc[3], a.x, w3);
        ffma2(acc[4], a.y, w0);
        ffma2(acc[5], a.y, w1);
        ffma2(acc[6], a.y, w2);
        ffma2(acc[7], a.y, w3);
    }
}

__global__ void __launch_bounds__(RTHREADS, 1) gru_rec_kernel(
    const float* __restrict__ Wz,
    const float* __restrict__ Wr,
    const float* __restrict__ Wm,
    float* __restrict__ out)
{
    extern __shared__ float sm[];
    float* hs0 = sm;
    float* hs1 = sm + HS_SIZE;
    float* wsm = sm + W_OFF;
    float* red = sm + RED_OFF;

    const int tid = threadIdx.x;
    const int j0  = blockIdx.x * 8;
    const int warp = tid >> 5;

    // phase A roles: warp -> (gate, split-K quarter); lane -> (jq, bq)
    const int gA   = warp & 1;
    const int kqA  = warp >> 1;      // 0..3
    const int slotA = tid & 63;
    const int jqA  = (slotA >> 4) & 1;
    const int bqA  = slotA & 15;
    // phase B roles
    const int kqB  = warp;           // 0..7
    const int slotB = tid & 31;
    const int jqB  = (slotB >> 4) & 1;
    const int bqB  = slotB & 15;
    // staging roles
    const int sb  = tid >> 2;        // batch 0..63
    const int skq = tid & 3;

    // ---- preload persistent weight slices ----
    for (int f = tid; f < 6144; f += RTHREADS) {
        int g = f >> 11;
        int r = f & 2047;
        int k = r >> 1;
        int jh = r & 1;
        const float* W = (g == 0) ? Wz : ((g == 1) ? Wr : Wm);
        float4 v = *(const float4*)&W[(size_t)(IN_DIM + k) * HID + j0 + jh * 4];
        *(float4*)&wsm[g * W_GATE + k * 8 + jh * 4] = v;
    }
    unsigned mygen = ld_acq(&g_gen);
    __syncthreads();

    float zreg[4][4];
#pragma unroll
    for (int i = 0; i < 4; i++)
#pragma unroll
        for (int j = 0; j < 4; j++) zreg[i][j] = 0.f;

    const int jcolA = j0 + jqA * 4;
    const int jcolB = j0 + jqB * 4;

    for (int t = 0; t < SEQ; t++) {
        // ================= Phase A: z and r =================
        unsigned long long acc[8];
#pragma unroll
        for (int i = 0; i < 8; i++) acc[i] = 0ull;

        // owner prefetch (x, and h for the r gate) — stable during phase A
        float4 xpre[4], hpre[4];
        if (kqA == 0) {
#pragma unroll
            for (int bb = 0; bb < 4; bb++) {
                int b = bqA * 4 + bb;
                xpre[bb] = __ldcg((const float4*)&g_x[gA][((size_t)t * BATCH + b) * HID + jcolA]);
                if (gA == 1)
                    hpre[bb] = __ldcg((const float4*)&g_h[b * HID + jcolA]);
            }
        }

        const float* wbA = wsm + gA * W_GATE;
        float4 pv[4];
        stage_load(g_h, 0, sb, skq, pv);
        stage_store(hs0, sb, skq, pv);
        __syncthreads();

#pragma unroll 1
        for (int c = 0; c < NCHUNK; c++) {
            float* cur = (c & 1) ? hs1 : hs0;
            float* nxt = (c & 1) ? hs0 : hs1;
            if (c < NCHUNK - 1) stage_load(g_h, (c + 1) * KC, sb, skq, pv);
            // FIX: weight base advances by chunk (c*KC rows of 8 floats)
            mm_chunk<16>(cur, wbA + c * KC * 8, kqA * 16, bqA, jqA, acc);
            if (c < NCHUNK - 1) stage_store(nxt, sb, skq, pv);
            __syncthreads();
        }

        if (kqA > 0) {
            unsigned long long* rp = (unsigned long long*)&red[((kqA - 1) * 64 + slotA) * 16];
#pragma unroll
            for (int i = 0; i < 8; i++) rp[i] = acc[i];
        }
        __syncthreads();
        if (kqA == 0) {
#pragma unroll
            for (int r2 = 0; r2 < 3; r2++) {
                const unsigned long long* rp =
                    (const unsigned long long*)&red[(r2 * 64 + slotA) * 16];
#pragma unroll
                for (int i = 0; i < 8; i++) acc[i] = addf32x2(acc[i], rp[i]);
            }
            float dv[4][4];
#pragma unroll
            for (int p = 0; p < 2; p++)
#pragma unroll
                for (int j = 0; j < 4; j++)
                    unpk(acc[p * 4 + j], dv[2 * p][j], dv[2 * p + 1][j]);

#pragma unroll
            for (int bb = 0; bb < 4; bb++) {
                int b = bqA * 4 + bb;
                float4 x4 = xpre[bb];
                float v0 = sigmoidf_(x4.x + dv[bb][0]);
                float v1 = sigmoidf_(x4.y + dv[bb][1]);
                float v2 = sigmoidf_(x4.z + dv[bb][2]);
                float v3 = sigmoidf_(x4.w + dv[bb][3]);
                if (gA == 0) {
                    zreg[bb][0] = v0; zreg[bb][1] = v1; zreg[bb][2] = v2; zreg[bb][3] = v3;
                } else {
                    float4 h4 = hpre[bb];
                    float4 rh4;
                    rh4.x = v0 * h4.x;
                    rh4.y = v1 * h4.y;
                    rh4.z = v2 * h4.z;
                    rh4.w = v3 * h4.w;
                    __stcg((float4*)&g_rh[b * HID + jcolA], rh4);
                }
            }
        }
        mygen++;
        gbar(mygen);   // rh globally visible

        // ================= Phase B: m gate =================
#pragma unroll
        for (int i = 0; i < 8; i++) acc[i] = 0ull;

        float4 xmpre[4], hbpre[4];
        if (kqB == 0) {
#pragma unroll
            for (int bb = 0; bb < 4; bb++) {
                int b = bqB * 4 + bb;
                xmpre[bb] = __ldcg((const float4*)&g_x[2][((size_t)t * BATCH + b) * HID + jcolB]);
                hbpre[bb] = __ldcg((const float4*)&g_h[b * HID + jcolB]);
            }
        }

        const float* wbB = wsm + 2 * W_GATE;
        stage_load(g_rh, 0, sb, skq, pv);
        stage_store(hs0, sb, skq, pv);
        __syncthreads();

#pragma unroll 1
        for (int c = 0; c < NCHUNK; c++) {
            float* cur = (c & 1) ? hs1 : hs0;
            float* nxt = (c & 1) ? hs0 : hs1;
            if (c < NCHUNK - 1) stage_load(g_rh, (c + 1) * KC, sb, skq, pv);
            // FIX: weight base advances by chunk
            mm_chunk<8>(cur, wbB + c * KC * 8, kqB * 8, bqB, jqB, acc);
            if (c < NCHUNK - 1) stage_store(nxt, sb, skq, pv);
            __syncthreads();
        }

        if (kqB > 0) {
            unsigned long long* rp = (unsigned long long*)&red[((kqB - 1) * 32 + slotB) * 16];
#pragma unroll
            for (int i = 0; i < 8; i++) rp[i] = acc[i];
        }
        __syncthreads();
        if (kqB == 0) {
#pragma unroll
            for (int r2 = 0; r2 < 7; r2++) {
                const unsigned long long* rp =
                    (const unsigned long long*)&red[(r2 * 32 + slotB) * 16];
#pragma unroll
                for (int i = 0; i < 8; i++) acc[i] = addf32x2(acc[i], rp[i]);
            }
            float dv[4][4];
#pragma unroll
            for (int p = 0; p < 2; p++)
#pragma unroll
                for (int j = 0; j < 4; j++)
                    unpk(acc[p * 4 + j], dv[2 * p][j], dv[2 * p + 1][j]);

#pragma unroll
            for (int bb = 0; bb < 4; bb++) {
                int b = bqB * 4 + bb;
                float4 xm4 = xmpre[bb];
                float4 h4  = hbpre[bb];
                float hn[4];
                float pre0 = xm4.x + dv[bb][0];
                float pre1 = xm4.y + dv[bb][1];
                float pre2 = xm4.z + dv[bb][2];
                float pre3 = xm4.w + dv[bb][3];
                hn[0] = h4.x + zreg[bb][0] * (tanhf(pre0) - h4.x);
                hn[1] = h4.y + zreg[bb][1] * (tanhf(pre1) - h4.y);
                hn[2] = h4.z + zreg[bb][2] * (tanhf(pre2) - h4.z);
                hn[3] = h4.w + zreg[bb][3] * (tanhf(pre3) - h4.w);
                float4 hn4 = make_float4(hn[0], hn[1], hn[2], hn[3]);
                __stcg((float4*)&g_h[b * HID + jcolB], hn4);
                __stcg((float4*)&out[((size_t)b * SEQ + t) * HID + jcolB], hn4);
            }
        }
        mygen++;
        gbar(mygen);   // h_new globally visible
    }
}

// ---------------------------------------------------------------------------
extern "C" void kernel_launch(void* const* d_in, const int* in_sizes, int n_in,
                              void* d_out, int out_size)
{
    const float* E  = (const float*)d_in[0];
    const float* h0 = (const float*)d_in[1];
    const float* Wz = (const float*)d_in[2];
    const float* bz = (const float*)d_in[3];
    const float* Wr = (const float*)d_in[4];
    const float* br = (const float*)d_in[5];
    const float* Wm = (const float*)d_in[6];
    const float* bm = (const float*)d_in[7];
    float* out = (float*)d_out;

    static int attr_done = 0;
    if (!attr_done) {
        cudaFuncSetAttribute(gru_rec_kernel,
                             cudaFuncAttributeMaxDynamicSharedMemorySize, SMEM_BYTES);
        attr_done = 1;
    }

    init_h_kernel<<<64, 256>>>(h0);

    dim3 gg(HID / BN, (SEQ * BATCH) / BM, 3);
    x_gemm_kernel<<<gg, 256>>>(E, Wz, bz, Wr, br, Wm, bm);

    gru_rec_kernel<<<NCTA, RTHREADS, SMEM_BYTES>>>(Wz, Wr, Wm, out);
}

// round 7
// speedup vs baseline: 2.5030x; 1.0722x over previous
#include <cuda_runtime.h>
#include <math.h>
#include <stdint.h>

#define SEQ 512
#define BATCH 64
#define IN_DIM 512
#define HID 1024

#define NCTA 128
#define RTHREADS 256
#define KC 128
#define NCHUNK (HID / KC)

// smem partition (floats)
#define HS_STRIDE 68                 // 64 batches + pad
#define HS_SIZE   (KC * HS_STRIDE)   // 8704
#define W_OFF     (2 * HS_SIZE)      // 17408
#define W_GATE    (HID * 8)          // 8192
#define RED_OFF   (W_OFF + 3 * W_GATE)   // 41984
#define SMEM_FLOATS (RED_OFF + 3584)     // 45568
#define SMEM_BYTES  (SMEM_FLOATS * 4)    // 182272

#define FLAG_STRIDE 32               // one flag per 128B line

// ---------------- scratch ----------------
__device__ float g_x[3][(size_t)SEQ * BATCH * HID];
__device__ float g_h[BATCH * HID];
__device__ float g_rh[BATCH * HID];
__device__ unsigned g_flags[NCTA * FLAG_STRIDE];  // zero-init; monotonic

__device__ __forceinline__ float sigmoidf_(float x) { return 1.0f / (1.0f + expf(-x)); }

// ---------------- f32x2 helpers ----------------
__device__ __forceinline__ void ffma2(unsigned long long& d, unsigned long long a, unsigned long long w) {
    asm("fma.rn.f32x2 %0, %1, %2, %0;" : "+l"(d) : "l"(a), "l"(w));
}
__device__ __forceinline__ unsigned long long addf32x2(unsigned long long a, unsigned long long b) {
    unsigned long long d;
    asm("add.rn.f32x2 %0, %1, %2;" : "=l"(d) : "l"(a), "l"(b));
    return d;
}
__device__ __forceinline__ unsigned long long dup2(float w) {
    unsigned long long d;
    unsigned u = __float_as_uint(w);
    asm("mov.b64 %0, {%1, %1};" : "=l"(d) : "r"(u));
    return d;
}
__device__ __forceinline__ void unpk(unsigned long long v, float& lo, float& hi) {
    unsigned x, y;
    asm("mov.b64 {%0, %1}, %2;" : "=r"(x), "=r"(y) : "l"(v));
    lo = __uint_as_float(x);
    hi = __uint_as_float(y);
}

// ---------------- sync helpers ----------------
__device__ __forceinline__ unsigned ld_acq(const unsigned* p) {
    unsigned v;
    asm volatile("ld.acquire.gpu.u32 %0, [%1];" : "=r"(v) : "l"(p) : "memory");
    return v;
}
// Distributed-flag global barrier: no contended atomics.
// Every thread fences its own prior global stores, CTA syncs, thread 0
// release-stores this CTA's flag, threads 0..NCTA-1 each poll one flag.
__device__ __forceinline__ void gbar(unsigned target) {
    __threadfence();
    __syncthreads();
    if (threadIdx.x == 0) {
        asm volatile("st.release.gpu.u32 [%0], %1;"
                     :: "l"(&g_flags[blockIdx.x * FLAG_STRIDE]), "r"(target) : "memory");
    }
    if (threadIdx.x < NCTA) {
        const unsigned* p = &g_flags[threadIdx.x * FLAG_STRIDE];
        while ((int)(ld_acq(p) - target) < 0) { }
    }
    __syncthreads();
}

// ---------------------------------------------------------------------------
__global__ void init_h_kernel(const float* __restrict__ h0) {
    int i = blockIdx.x * blockDim.x + threadIdx.x;
    for (; i < BATCH * HID; i += gridDim.x * blockDim.x)
        g_h[i] = h0[i];
}

// ---------------------------------------------------------------------------
// Precompute x-projections, FFMA2 inner loop (m-pair packing).
// ---------------------------------------------------------------------------
#define BM 128
#define BN 64
#define BK 32

__global__ void __launch_bounds__(256) x_gemm_kernel(
    const float* __restrict__ E,
    const float* __restrict__ Wz, const float* __restrict__ bz,
    const float* __restrict__ Wr, const float* __restrict__ br,
    const float* __restrict__ Wm, const float* __restrict__ bm)
{
    const int gate = blockIdx.z;
    const float* W    = (gate == 0) ? Wz : (gate == 1) ? Wr : Wm;
    const float* bias = (gate == 0) ? bz : (gate == 1) ? br : bm;
    float* OUT = g_x[gate];

    __shared__ float as[BK][BM + 4];   // [k][m]
    __shared__ float bs[BK][BN + 4];   // [k][n]

    const int tid   = threadIdx.x;
    const int mBase = blockIdx.y * BM;
    const int nBase = blockIdx.x * BN;
    const int tx = tid & 15;   // 4 n-cols
    const int ty = tid >> 4;   // 8 m-rows

    unsigned long long acc2[4][4];   // [m-pair][n]
#pragma unroll
    for (int i = 0; i < 4; i++)
#pragma unroll
        for (int j = 0; j < 4; j++) acc2[i][j] = 0ull;

    for (int k0 = 0; k0 < IN_DIM; k0 += BK) {
#pragma unroll
        for (int i = 0; i < 4; i++) {
            int f = tid + i * 256;
            int m = f >> 3;
            int kq = f & 7;
            float4 v = *(const float4*)&E[(size_t)(mBase + m) * IN_DIM + k0 + kq * 4];
            as[kq * 4 + 0][m] = v.x;
            as[kq * 4 + 1][m] = v.y;
            as[kq * 4 + 2][m] = v.z;
            as[kq * 4 + 3][m] = v.w;
        }
#pragma unroll
        for (int i = 0; i < 2; i++) {
            int f = tid + i * 256;
            int r = f >> 4;
            int cq = f & 15;
            float4 v = *(const float4*)&W[(size_t)(k0 + r) * HID + nBase + cq * 4];
            *(float4*)&bs[r][cq * 4] = v;
        }
        __syncthreads();

#pragma unroll 8
        for (int k = 0; k < BK; k++) {
            unsigned long long a[4];
#pragma unroll
            for (int i = 0; i < 4; i++)
                a[i] = *(const unsigned long long*)&as[k][ty * 8 + 2 * i];
            float4 bvv = *(const float4*)&bs[k][tx * 4];
            unsigned long long b0 = dup2(bvv.x), b1 = dup2(bvv.y),
                               b2 = dup2(bvv.z), b3 = dup2(bvv.w);
#pragma unroll
            for (int i = 0; i < 4; i++) {
                ffma2(acc2[i][0], a[i], b0);
                ffma2(acc2[i][1], a[i], b1);
                ffma2(acc2[i][2], a[i], b2);
                ffma2(acc2[i][3], a[i], b3);
            }
        }
        __syncthreads();
    }

    float dv[8][4];
#pragma unroll
    for (int i = 0; i < 4; i++)
#pragma unroll
        for (int j = 0; j < 4; j++)
            unpk(acc2[i][j], dv[2 * i][j], dv[2 * i + 1][j]);

    const float4 bv = *(const float4*)&bias[nBase + tx * 4];
#pragma unroll
    for (int p = 0; p < 8; p++) {
        int m = mBase + ty * 8 + p;
        float4 o;
        o.x = dv[p][0] + bv.x;
        o.y = dv[p][1] + bv.y;
        o.z = dv[p][2] + bv.z;
        o.w = dv[p][3] + bv.w;
        *(float4*)&OUT[(size_t)m * HID + nBase + tx * 4] = o;
    }
}

// ---------------------------------------------------------------------------
// Recurrence v4: KC=128 (8 chunks/phase), distributed-flag barrier,
// persistent weights, double-buffered h staging, FFMA2 inner loop.
// ---------------------------------------------------------------------------
__device__ __forceinline__ void stage_load(const float* __restrict__ src, int k0,
                                           int sb, int skq, float4 pv[8]) {
#pragma unroll
    for (int i = 0; i < 8; i++) {
        int kq = i * 4 + skq;
        pv[i] = __ldcg((const float4*)&src[(size_t)sb * HID + k0 + kq * 4]);
    }
}
__device__ __forceinline__ void stage_store(float* __restrict__ hb,
                                            int sb, int skq, const float4 pv[8]) {
#pragma unroll
    for (int i = 0; i < 8; i++) {
        int kq = i * 4 + skq;
        hb[(kq * 4 + 0) * HS_STRIDE + sb] = pv[i].x;
        hb[(kq * 4 + 1) * HS_STRIDE + sb] = pv[i].y;
        hb[(kq * 4 + 2) * HS_STRIDE + sb] = pv[i].z;
        hb[(kq * 4 + 3) * HS_STRIDE + sb] = pv[i].w;
    }
}

// hb: staged chunk [KC][HS_STRIDE]; wb: weight rows for THIS chunk ([KC][8]).
template <int KN>
__device__ __forceinline__ void mm_chunk(const float* __restrict__ hb,
                                         const float* __restrict__ wb,
                                         int kbeg, int bq, int jq,
                                         unsigned long long acc[8]) {
    const float* hp = hb + kbeg * HS_STRIDE + bq * 4;
    const float* wp = wb + kbeg * 8 + jq * 4;
#pragma unroll
    for (int i = 0; i < KN; i++) {
        ulonglong2 a = *(const ulonglong2*)(hp + i * HS_STRIDE);
        float4 wv = *(const float4*)(wp + i * 8);
        unsigned long long w0 = dup2(wv.x), w1 = dup2(wv.y), w2 = dup2(wv.z), w3 = dup2(wv.w);
        ffma2(acc[0], a.x, w0);
        ffma2(acc[1], a.x, w1);
        ffma2(acc[2], a.x, w2);
        ffma2(acc[3], a.x, w3);
        ffma2(acc[4], a.y, w0);
        ffma2(acc[5], a.y, w1);
        ffma2(acc[6], a.y, w2);
        ffma2(acc[7], a.y, w3);
    }
}

__global__ void __launch_bounds__(RTHREADS, 1) gru_rec_kernel(
    const float* __restrict__ Wz,
    const float* __restrict__ Wr,
    const float* __restrict__ Wm,
    float* __restrict__ out)
{
    extern __shared__ float sm[];
    float* hs0 = sm;
    float* hs1 = sm + HS_SIZE;
    float* wsm = sm + W_OFF;
    float* red = sm + RED_OFF;

    const int tid = threadIdx.x;
    const int j0  = blockIdx.x * 8;
    const int warp = tid >> 5;

    // phase A roles
    const int gA   = warp & 1;
    const int kqA  = warp >> 1;      // 0..3 (split-K quarter of KC)
    const int slotA = tid & 63;
    const int jqA  = (slotA >> 4) & 1;
    const int bqA  = slotA & 15;
    // phase B roles
    const int kqB  = warp;           // 0..7 (split-K eighth of KC)
    const int slotB = tid & 31;
    const int jqB  = (slotB >> 4) & 1;
    const int bqB  = slotB & 15;
    // staging roles
    const int sb  = tid >> 2;        // batch 0..63
    const int skq = tid & 3;

    // ---- preload persistent weight slices (once) ----
    for (int f = tid; f < 6144; f += RTHREADS) {
        int g = f >> 11;
        int r = f & 2047;
        int k = r >> 1;
        int jh = r & 1;
        const float* W = (g == 0) ? Wz : ((g == 1) ? Wr : Wm);
        float4 v = *(const float4*)&W[(size_t)(IN_DIM + k) * HID + j0 + jh * 4];
        *(float4*)&wsm[g * W_GATE + k * 8 + jh * 4] = v;
    }
    unsigned mygen = ld_acq(&g_flags[blockIdx.x * FLAG_STRIDE]); // own flag only
    __syncthreads();

    float zreg[4][4];
#pragma unroll
    for (int i = 0; i < 4; i++)
#pragma unroll
        for (int j = 0; j < 4; j++) zreg[i][j] = 0.f;

    const int jcolA = j0 + jqA * 4;
    const int jcolB = j0 + jqB * 4;

    for (int t = 0; t < SEQ; t++) {
        // ================= Phase A: z and r =================
        unsigned long long acc[8];
#pragma unroll
        for (int i = 0; i < 8; i++) acc[i] = 0ull;

        float4 xpre[4], hpre[4];
        if (kqA == 0) {
#pragma unroll
            for (int bb = 0; bb < 4; bb++) {
                int b = bqA * 4 + bb;
                xpre[bb] = __ldcg((const float4*)&g_x[gA][((size_t)t * BATCH + b) * HID + jcolA]);
                if (gA == 1)
                    hpre[bb] = __ldcg((const float4*)&g_h[b * HID + jcolA]);
            }
        }

        const float* wbA = wsm + gA * W_GATE;
        float4 pv[8];
        stage_load(g_h, 0, sb, skq, pv);
        stage_store(hs0, sb, skq, pv);
        __syncthreads();

#pragma unroll 1
        for (int c = 0; c < NCHUNK; c++) {
            float* cur = (c & 1) ? hs1 : hs0;
            float* nxt = (c & 1) ? hs0 : hs1;
            if (c < NCHUNK - 1) stage_load(g_h, (c + 1) * KC, sb, skq, pv);
            mm_chunk<32>(cur, wbA + c * KC * 8, kqA * 32, bqA, jqA, acc);
            if (c < NCHUNK - 1) stage_store(nxt, sb, skq, pv);
            __syncthreads();
        }

        if (kqA > 0) {
            unsigned long long* rp = (unsigned long long*)&red[((kqA - 1) * 64 + slotA) * 16];
#pragma unroll
            for (int i = 0; i < 8; i++) rp[i] = acc[i];
        }
        __syncthreads();
        if (kqA == 0) {
#pragma unroll
            for (int r2 = 0; r2 < 3; r2++) {
                const unsigned long long* rp =
                    (const unsigned long long*)&red[(r2 * 64 + slotA) * 16];
#pragma unroll
                for (int i = 0; i < 8; i++) acc[i] = addf32x2(acc[i], rp[i]);
            }
            float dv[4][4];
#pragma unroll
            for (int p = 0; p < 2; p++)
#pragma unroll
                for (int j = 0; j < 4; j++)
                    unpk(acc[p * 4 + j], dv[2 * p][j], dv[2 * p + 1][j]);

#pragma unroll
            for (int bb = 0; bb < 4; bb++) {
                int b = bqA * 4 + bb;
                float4 x4 = xpre[bb];
                float v0 = sigmoidf_(x4.x + dv[bb][0]);
                float v1 = sigmoidf_(x4.y + dv[bb][1]);
                float v2 = sigmoidf_(x4.z + dv[bb][2]);
                float v3 = sigmoidf_(x4.w + dv[bb][3]);
                if (gA == 0) {
                    zreg[bb][0] = v0; zreg[bb][1] = v1; zreg[bb][2] = v2; zreg[bb][3] = v3;
                } else {
                    float4 h4 = hpre[bb];
                    float4 rh4;
                    rh4.x = v0 * h4.x;
                    rh4.y = v1 * h4.y;
                    rh4.z = v2 * h4.z;
                    rh4.w = v3 * h4.w;
                    __stcg((float4*)&g_rh[b * HID + jcolA], rh4);
                }
            }
        }
        mygen++;
        gbar(mygen);   // rh globally visible

        // ================= Phase B: m gate =================
#pragma unroll
        for (int i = 0; i < 8; i++) acc[i] = 0ull;

        float4 xmpre[4], hbpre[4];
        if (kqB == 0) {
#pragma unroll
            for (int bb = 0; bb < 4; bb++) {
                int b = bqB * 4 + bb;
                xmpre[bb] = __ldcg((const float4*)&g_x[2][((size_t)t * BATCH + b) * HID + jcolB]);
                hbpre[bb] = __ldcg((const float4*)&g_h[b * HID + jcolB]);
            }
        }

        const float* wbB = wsm + 2 * W_GATE;
        stage_load(g_rh, 0, sb, skq, pv);
        stage_store(hs0, sb, skq, pv);
        __syncthreads();

#pragma unroll 1
        for (int c = 0; c < NCHUNK; c++) {
            float* cur = (c & 1) ? hs1 : hs0;
            float* nxt = (c & 1) ? hs0 : hs1;
            if (c < NCHUNK - 1) stage_load(g_rh, (c + 1) * KC, sb, skq, pv);
            mm_chunk<16>(cur, wbB + c * KC * 8, kqB * 16, bqB, jqB, acc);
            if (c < NCHUNK - 1) stage_store(nxt, sb, skq, pv);
            __syncthreads();
        }

        if (kqB > 0) {
            unsigned long long* rp = (unsigned long long*)&red[((kqB - 1) * 32 + slotB) * 16];
#pragma unroll
            for (int i = 0; i < 8; i++) rp[i] = acc[i];
        }
        __syncthreads();
        if (kqB == 0) {
#pragma unroll
            for (int r2 = 0; r2 < 7; r2++) {
                const unsigned long long* rp =
                    (const unsigned long long*)&red[(r2 * 32 + slotB) * 16];
#pragma unroll
                for (int i = 0; i < 8; i++) acc[i] = addf32x2(acc[i], rp[i]);
            }
            float dv[4][4];
#pragma unroll
            for (int p = 0; p < 2; p++)
#pragma unroll
                for (int j = 0; j < 4; j++)
                    unpk(acc[p * 4 + j], dv[2 * p][j], dv[2 * p + 1][j]);

#pragma unroll
            for (int bb = 0; bb < 4; bb++) {
                int b = bqB * 4 + bb;
                float4 xm4 = xmpre[bb];
                float4 h4  = hbpre[bb];
                float hn[4];
                float pre0 = xm4.x + dv[bb][0];
                float pre1 = xm4.y + dv[bb][1];
                float pre2 = xm4.z + dv[bb][2];
                float pre3 = xm4.w + dv[bb][3];
                hn[0] = h4.x + zreg[bb][0] * (tanhf(pre0) - h4.x);
                hn[1] = h4.y + zreg[bb][1] * (tanhf(pre1) - h4.y);
                hn[2] = h4.z + zreg[bb][2] * (tanhf(pre2) - h4.z);
                hn[3] = h4.w + zreg[bb][3] * (tanhf(pre3) - h4.w);
                float4 hn4 = make_float4(hn[0], hn[1], hn[2], hn[3]);
                __stcg((float4*)&g_h[b * HID + jcolB], hn4);
                __stcg((float4*)&out[((size_t)b * SEQ + t) * HID + jcolB], hn4);
            }
        }
        mygen++;
        gbar(mygen);   // h_new globally visible
    }
}

// ---------------------------------------------------------------------------
extern "C" void kernel_launch(void* const* d_in, const int* in_sizes, int n_in,
                              void* d_out, int out_size)
{
    const float* E  = (const float*)d_in[0];
    const float* h0 = (const float*)d_in[1];
    const float* Wz = (const float*)d_in[2];
    const float* bz = (const float*)d_in[3];
    const float* Wr = (const float*)d_in[4];
    const float* br = (const float*)d_in[5];
    const float* Wm = (const float*)d_in[6];
    const float* bm = (const float*)d_in[7];
    float* out = (float*)d_out;

    static int attr_done = 0;
    if (!attr_done) {
        cudaFuncSetAttribute(gru_rec_kernel,
                             cudaFuncAttributeMaxDynamicSharedMemorySize, SMEM_BYTES);
        attr_done = 1;
    }

    init_h_kernel<<<64, 256>>>(h0);

    dim3 gg(HID / BN, (SEQ * BATCH) / BM, 3);
    x_gemm_kernel<<<gg, 256>>>(E, Wz, bz, Wr, br, Wm, bm);

    gru_rec_kernel<<<NCTA, RTHREADS, SMEM_BYTES>>>(Wz, Wr, Wm, out);
}